// round 11
// baseline (speedup 1.0000x reference)
#include <cuda_runtime.h>
#include <cuda_bf16.h>
#include <math.h>

// Problem dims: H=256, B=64, L=128, LABEL=128
// s = t*64 + b, S = 8192 sequential cells.

#define NSTEPS 8192
#define CHAIN_CTAS 16             // one 16-CTA cluster (non-portable size)
#define GEMM_BLOCKS 2048
#define MAIL_DEPTH 67             // odd, >=65 => structurally reuse-safe
#define MAIL_SLOT 144             // u64 words/slot: 16 groups * 9 (8 pairs + 1 pad)
// dynamic smem request: big enough that NO two blocks co-reside on an SM
// (152KB*2 > 228KB) -> GEMM blocks can never share an SM with a chain CTA.
#define DYN_SMEM_BYTES (152 * 1024)

// Scratch (device globals: allocation-free rule)
__device__ float    g_G[8192u * 1024u];  // 32 MB: input gates + bias
__device__ float    g_H[8192u * 256u];   // 8 MB: exact h history for fc
__device__ unsigned g_gdone[128];        // per-M-tile completion counters

// ---------------------------------------------------------------------------
// helpers
// ---------------------------------------------------------------------------
__device__ __forceinline__ unsigned ld_acq32(const unsigned* p) {
    unsigned v;
    asm volatile("ld.acquire.gpu.global.b32 %0, [%1];" : "=r"(v) : "l"(p) : "memory");
    return v;
}
__device__ __forceinline__ unsigned long long pk2(float lo, float hi) {
    unsigned long long r;
    asm("mov.b64 %0, {%1, %2};" : "=l"(r) : "f"(lo), "f"(hi));
    return r;
}
__device__ __forceinline__ void upk2(unsigned long long v, float& lo, float& hi) {
    asm("mov.b64 {%0, %1}, %2;" : "=f"(lo), "=f"(hi) : "l"(v));
}
__device__ __forceinline__ unsigned long long ffma2(
    unsigned long long a, unsigned long long b, unsigned long long c) {
    unsigned long long d;
    asm("fma.rn.f32x2 %0, %1, %2, %3;" : "=l"(d) : "l"(a), "l"(b), "l"(c));
    return d;
}
__device__ __forceinline__ unsigned smem_u32(const void* p) {
    unsigned a;
    asm("{ .reg .u64 t; cvta.to.shared.u64 t, %1; cvt.u32.u64 %0, t; }"
        : "=r"(a) : "l"(p));
    return a;
}
__device__ __forceinline__ unsigned mapa_rank(unsigned laddr, unsigned rank) {
    unsigned r;
    asm("mapa.shared::cluster.u32 %0, %1, %2;" : "=r"(r) : "r"(laddr), "r"(rank));
    return r;
}
// remote push: cluster-scope relaxed (morally strong, b64 no-tear)
__device__ __forceinline__ void st_clu64(unsigned addr, unsigned long long v) {
    asm volatile("st.relaxed.cluster.shared::cluster.b64 [%0], %1;"
                 :: "r"(addr), "l"(v) : "memory");
}
// local mailbox read: plain LDS path, volatile (morally strong, re-read forced)
__device__ __forceinline__ unsigned long long ld_vol64(unsigned addr) {
    unsigned long long v;
    asm volatile("ld.volatile.shared.b64 %0, [%1];" : "=l"(v) : "r"(addr) : "memory");
    return v;
}
__device__ __forceinline__ float fast_sigmoid(float x) {
    return __fdividef(1.f, 1.f + __expf(-x));
}
__device__ __forceinline__ float fast_tanh(float x) {
    return 1.f - __fdividef(2.f, __expf(2.f * x) + 1.f);
}

// ---------------------------------------------------------------------------
// GEMM body (proven tile code): G[s][j] = feats[s].W_ih[j][0:1024] + bias[j]
// ---------------------------------------------------------------------------
__device__ void gemm_body(
    float* smem, int gb,
    const float* __restrict__ x, const float* __restrict__ hi,
    const float* __restrict__ W_ih,
    const float* __restrict__ b_ih, const float* __restrict__ b_hh)
{
    float (*As)[68] = (float(*)[68])smem;
    float (*Bs)[68] = (float(*)[68])(smem + 16 * 68);

    const int tid = threadIdx.x;
    const int bn  = gb & 15;
    const int bm  = gb >> 4;           // M tiles complete in s-order
    const int tx  = tid & 15;
    const int ty  = tid >> 4;

    const int lm  = tid >> 2;
    const int lk4 = (tid & 3) * 4;

    const int s  = bm * 64 + lm;
    const int t  = s >> 6, b = s & 63;
    const float* xrow  = &x [((size_t)(b * 128 + t)) << 9];
    const float* hirow = &hi[((size_t)(b * 128 + t)) << 9];
    const float* wrow  = &W_ih[(size_t)(bn * 64 + (tid >> 2)) * 1280];

    float acc[4][4] = {};

    for (int kt = 0; kt < 64; kt++) {
        const int kbase = kt * 16 + lk4;
        float4 av;
        if (kbase < 512) av = *(const float4*)&xrow[kbase];
        else             av = *(const float4*)&hirow[kbase - 512];
        As[lk4 + 0][lm] = av.x;
        As[lk4 + 1][lm] = av.y;
        As[lk4 + 2][lm] = av.z;
        As[lk4 + 3][lm] = av.w;
        float4 bv = *(const float4*)&wrow[kbase];
        Bs[lk4 + 0][tid >> 2] = bv.x;
        Bs[lk4 + 1][tid >> 2] = bv.y;
        Bs[lk4 + 2][tid >> 2] = bv.z;
        Bs[lk4 + 3][tid >> 2] = bv.w;
        __syncthreads();

#pragma unroll
        for (int kk = 0; kk < 16; kk++) {
            float ar[4], br[4];
#pragma unroll
            for (int i = 0; i < 4; i++) ar[i] = As[kk][ty * 4 + i];
#pragma unroll
            for (int j = 0; j < 4; j++) br[j] = Bs[kk][tx * 4 + j];
#pragma unroll
            for (int i = 0; i < 4; i++)
#pragma unroll
                for (int j = 0; j < 4; j++)
                    acc[i][j] = fmaf(ar[i], br[j], acc[i][j]);
        }
        __syncthreads();
    }

    const int col0 = bn * 64 + tx * 4;
    float bias[4];
#pragma unroll
    for (int j = 0; j < 4; j++) bias[j] = b_ih[col0 + j] + b_hh[col0 + j];
#pragma unroll
    for (int i = 0; i < 4; i++) {
        const size_t row = (size_t)(bm * 64 + ty * 4 + i);
        float4 v;
        v.x = acc[i][0] + bias[0];
        v.y = acc[i][1] + bias[1];
        v.z = acc[i][2] + bias[2];
        v.w = acc[i][3] + bias[3];
        *(float4*)&g_G[row * 1024 + col0] = v;
    }

    __threadfence();
    __syncthreads();
    if (tid == 0) atomicAdd(&g_gdone[bm], 1u);
}

// ---------------------------------------------------------------------------
// Chain body (R9-proven structure): ONE cluster of 16 CTAs x 256 threads,
// no per-step barrier. CTA k owns h-indices 16k..16k+15; half-warp g2 of
// warp w owns jj = 16k+2w+g2; lane cg = lane&15 handles cols [16cg,16cg+16)
// of BOTH h and out_prev (64 FFMA2, packed register weights).
// Mailbox pair word = {h[2p+1] | h[2p]} with step stamp s&3 in h0's 2 LSBs.
// R10 deltas: poll loads software-pipelined ahead of the out_prev FMA phase;
// all local mailbox reads via ld.volatile.shared (LDS path).
// ---------------------------------------------------------------------------
__device__ void chain_body(
    unsigned long long* mail, int k,
    const float* __restrict__ W_ih, const float* __restrict__ W_hh)
{
    const int tid  = threadIdx.x;
    const int warp = tid >> 5;
    const int lane = tid & 31;
    const int g2   = lane >> 4;
    const int cg   = lane & 15;

    const int jj = k * 16 + 2 * warp + g2;  // owned h-index

    // Register-resident packed weights: 4 gate rows x 8 col-pairs, h + out_prev
    unsigned long long wh[4][8], wo[4][8];
#pragma unroll
    for (int r = 0; r < 4; r++) {
        const float* whrow = &W_hh[(size_t)(jj + 256 * r) * 256];
        const float* worow = &W_ih[(size_t)(jj + 256 * r) * 1280 + 1024];
#pragma unroll
        for (int c = 0; c < 8; c++) {
            const int col = cg * 16 + 2 * c;
            wh[r][c] = pk2(whrow[col], whrow[col + 1]);
            wo[r][c] = pk2(worow[col], worow[col + 1]);
        }
    }

    // init mailbox: slot x gets stamp (x&3)^1 (never matches its first writer)
    for (int x = 0; x < MAIL_DEPTH; x++) {
        const unsigned long long iw = (unsigned long long)((x & 3) ^ 1);
        for (int i = tid; i < MAIL_SLOT; i += 256) mail[x * MAIL_SLOT + i] = iw;
    }

    const unsigned mail_base = smem_u32(mail);
    const unsigned rd_off    = (unsigned)(9 * cg) * 8u;          // my 8-pair group
    const unsigned push_off  = (unsigned)(9 * k + warp) * 8u;    // my pair word

    float c_state = 0.f;   // replicated per lane (bit-identical by construction)

    __syncthreads();
    // cluster barrier: all mailboxes initialized before any push
    asm volatile("barrier.cluster.arrive.aligned;" ::: "memory");
    asm volatile("barrier.cluster.wait.aligned;" ::: "memory");

    int m = 0;  // s % 67
    for (int s = 0; s < NSTEPS; s++) {
        // G gating (once per 64 steps) + G prefetch
        if ((s & 63) == 0) {
            while (ld_acq32(&g_gdone[s >> 6]) < 16u) { }
        }
        float gpre[4];
        {
            const size_t gb = (size_t)s * 1024 + jj;
#pragma unroll
            for (int r = 0; r < 4; r++) gpre[r] = __ldcg(&g_G[gb + 256 * r]);
        }

        // ---- pipelined first poll attempt: issue loads NOW, check later
        const int h_slot = (m == 0) ? MAIL_DEPTH - 1 : m - 1;
        const unsigned ha = mail_base + (unsigned)(h_slot * MAIL_SLOT) * 8u + rd_off;
        unsigned long long v[8];
        if (s > 0) {
#pragma unroll
            for (int c = 0; c < 8; c++) v[c] = ld_vol64(ha + c * 8);
        }

        unsigned long long acc[4] = {0ull, 0ull, 0ull, 0ull};

        // ---- out_prev phase: h[s-64] from the old slot (local LDS)
        if (s >= 64) {
            const int o_slot = (m + 3 >= MAIL_DEPTH) ? m + 3 - MAIL_DEPTH : m + 3;
            const unsigned oa = mail_base + (unsigned)(o_slot * MAIL_SLOT) * 8u + rd_off;
#pragma unroll
            for (int c = 0; c < 8; c++) {
                const unsigned long long w = ld_vol64(oa + c * 8);
#pragma unroll
                for (int r = 0; r < 4; r++) acc[r] = ffma2(wo[r][c], w, acc[r]);
            }
        }

        // ---- stamp check (loads already in flight); retry on miss
        if (s > 0) {
            const unsigned stamp = (unsigned)((s - 1) & 3);
            for (;;) {
                bool ok = true;
#pragma unroll
                for (int c = 0; c < 8; c++) ok &= (((unsigned)v[c] & 3u) == stamp);
                if (ok) break;
#pragma unroll
                for (int c = 0; c < 8; c++) v[c] = ld_vol64(ha + c * 8);
            }
#pragma unroll
            for (int c = 0; c < 8; c++) {
#pragma unroll
                for (int r = 0; r < 4; r++) acc[r] = ffma2(wh[r][c], v[c], acc[r]);
            }
        }

        // butterfly reduce over the 16 col-groups: ALL lanes get the sums
        float g4[4];
#pragma unroll
        for (int r = 0; r < 4; r++) {
            float lo, hi2;
            upk2(acc[r], lo, hi2);
            g4[r] = lo + hi2;
        }
#pragma unroll
        for (int off = 1; off < 16; off <<= 1) {
#pragma unroll
            for (int r = 0; r < 4; r++)
                g4[r] += __shfl_xor_sync(0xffffffffu, g4[r], off);
        }

        // gates: redundant across the half-warp, c_state replicated
        const float iv = fast_sigmoid(g4[0] + gpre[0]);
        const float fv = fast_sigmoid(g4[1] + gpre[1]);
        const float gv = fast_tanh  (g4[2] + gpre[2]);
        const float ov = fast_sigmoid(g4[3] + gpre[3]);
        c_state = fv * c_state + iv * gv;
        const float hv = ov * fast_tanh(c_state);

        // exact mirror for fc (off the critical path)
        if (cg == 0) __stcg(&g_H[(size_t)s * 256 + jj], hv);

        // pair the halves and push: lanes 0..15 -> 16 cluster CTAs
        const float partner = __shfl_xor_sync(0xffffffffu, hv, 16);
        if (lane < 16) {
            unsigned long long pw = pk2(hv, partner);            // {h1 | h0}
            pw = (pw & ~3ull) | (unsigned long long)(s & 3);     // stamp in h0 LSBs
            const unsigned la = mail_base + (unsigned)(m * MAIL_SLOT) * 8u + push_off;
            st_clu64(mapa_rank(la, (unsigned)lane), pw);
        }

        m = (m + 1 == MAIL_DEPTH) ? 0 : m + 1;
    }

    // cluster barrier before exit: peers' smem must outlive in-flight pushes
    asm volatile("barrier.cluster.arrive.aligned;" ::: "memory");
    asm volatile("barrier.cluster.wait.aligned;" ::: "memory");
}

// ---------------------------------------------------------------------------
// Fused kernel: blocks 0..15 = the chain cluster; 16..2063 = GEMM tiles.
// 152KB dynamic smem per block -> strictly one block per SM: GEMM never
// co-resides with (and never slows) a chain CTA.
// ---------------------------------------------------------------------------
__global__ void __launch_bounds__(256) fused_kernel(
    const float* __restrict__ x, const float* __restrict__ hi,
    const float* __restrict__ W_ih, const float* __restrict__ W_hh,
    const float* __restrict__ b_ih, const float* __restrict__ b_hh)
{
    extern __shared__ unsigned long long dynsmem[];
    if (blockIdx.x < CHAIN_CTAS) {
        chain_body(dynsmem, blockIdx.x, W_ih, W_hh);
    } else {
        gemm_body((float*)dynsmem, blockIdx.x - CHAIN_CTAS, x, hi, W_ih, b_ih, b_hh);
    }
}

// ---------------------------------------------------------------------------
// Kernel C: out[b][t][l] = H[s] . W_fc[l] + b_fc[l], s = t*64+b
// ---------------------------------------------------------------------------
__global__ void __launch_bounds__(128) fc_kernel(
    const float* __restrict__ W_fc, const float* __restrict__ b_fc,
    float* __restrict__ out)
{
    __shared__ float hrow[8][256];
    const int s0 = blockIdx.x * 8;
    const int l  = threadIdx.x;

#pragma unroll
    for (int ss = 0; ss < 8; ss++) {
        hrow[ss][l]       = g_H[(size_t)(s0 + ss) * 256 + l];
        hrow[ss][128 + l] = g_H[(size_t)(s0 + ss) * 256 + 128 + l];
    }
    __syncthreads();

    float acc[8];
    const float bias = b_fc[l];
#pragma unroll
    for (int ss = 0; ss < 8; ss++) acc[ss] = bias;

    const float* wr = &W_fc[(size_t)l * 256];
#pragma unroll 4
    for (int j = 0; j < 256; j++) {
        const float wv = wr[j];
#pragma unroll
        for (int ss = 0; ss < 8; ss++)
            acc[ss] = fmaf(wv, hrow[ss][j], acc[ss]);
    }

#pragma unroll
    for (int ss = 0; ss < 8; ss++) {
        const int s = s0 + ss;
        const int t = s >> 6, b = s & 63;
        out[((size_t)b << 14) + (size_t)t * 128 + l] = acc[ss];
    }
}

// ---------------------------------------------------------------------------
extern "C" void kernel_launch(void* const* d_in, const int* in_sizes, int n_in,
                              void* d_out, int out_size)
{
    const float* x    = (const float*)d_in[0];
    const float* hi   = (const float*)d_in[1];
    const float* W_ih = (const float*)d_in[2];
    const float* W_hh = (const float*)d_in[3];
    const float* b_ih = (const float*)d_in[4];
    const float* b_hh = (const float*)d_in[5];
    const float* W_fc = (const float*)d_in[6];
    const float* b_fc = (const float*)d_in[7];
    float* out = (float*)d_out;

    // clear tile counters every call/replay (mailbox init is in-kernel)
    void* gp = nullptr;
    cudaGetSymbolAddress(&gp, g_gdone);
    cudaMemsetAsync(gp, 0, 128 * sizeof(unsigned));

    cudaFuncSetAttribute(fused_kernel,
                         cudaFuncAttributeMaxDynamicSharedMemorySize, DYN_SMEM_BYTES);
    cudaFuncSetAttribute(fused_kernel,
                         cudaFuncAttributeNonPortableClusterSizeAllowed, 1);

    cudaLaunchConfig_t cfg = {};
    cfg.gridDim  = dim3(CHAIN_CTAS + GEMM_BLOCKS, 1, 1);  // 2064 = 129 * 16
    cfg.blockDim = dim3(256, 1, 1);
    cfg.dynamicSmemBytes = DYN_SMEM_BYTES;
    cudaLaunchAttribute attrs[1];
    attrs[0].id = cudaLaunchAttributeClusterDimension;
    attrs[0].val.clusterDim.x = 16;
    attrs[0].val.clusterDim.y = 1;
    attrs[0].val.clusterDim.z = 1;
    cfg.attrs = attrs;
    cfg.numAttrs = 1;
    cudaLaunchKernelEx(&cfg, fused_kernel, x, hi, W_ih, W_hh, b_ih, b_hh);

    fc_kernel<<<NSTEPS / 8, 128>>>(W_fc, b_fc, out);
}

// round 12
// speedup vs baseline: 1.0284x; 1.0284x over previous
#include <cuda_runtime.h>
#include <cuda_bf16.h>
#include <math.h>

// Problem dims: H=256, B=64, L=128, LABEL=128
// s = t*64 + b, S = 8192 sequential cells.

#define NSTEPS 8192
#define CHAIN_CTAS 16             // one 16-CTA cluster (non-portable size)
#define GEMM_BLOCKS 2048
#define MAIL_DEPTH 67             // odd, >=65 => structurally reuse-safe
#define MAIL_SLOT 144             // u64 words/slot: 16 groups * 9 (8 pairs + 1 pad)

// Scratch (device globals: allocation-free rule)
__device__ float    g_G[8192u * 1024u];  // 32 MB: input gates + bias
__device__ float    g_H[8192u * 256u];   // 8 MB: exact h history for fc
__device__ unsigned g_gdone[128];        // per-M-tile completion counters

// ---------------------------------------------------------------------------
// helpers
// ---------------------------------------------------------------------------
__device__ __forceinline__ unsigned ld_acq32(const unsigned* p) {
    unsigned v;
    asm volatile("ld.acquire.gpu.global.b32 %0, [%1];" : "=r"(v) : "l"(p) : "memory");
    return v;
}
__device__ __forceinline__ unsigned long long pk2(float lo, float hi) {
    unsigned long long r;
    asm("mov.b64 %0, {%1, %2};" : "=l"(r) : "f"(lo), "f"(hi));
    return r;
}
__device__ __forceinline__ void upk2(unsigned long long v, float& lo, float& hi) {
    asm("mov.b64 {%0, %1}, %2;" : "=f"(lo), "=f"(hi) : "l"(v));
}
__device__ __forceinline__ unsigned long long ffma2(
    unsigned long long a, unsigned long long b, unsigned long long c) {
    unsigned long long d;
    asm("fma.rn.f32x2 %0, %1, %2, %3;" : "=l"(d) : "l"(a), "l"(b), "l"(c));
    return d;
}
__device__ __forceinline__ unsigned smem_u32(const void* p) {
    unsigned a;
    asm("{ .reg .u64 t; cvta.to.shared.u64 t, %1; cvt.u32.u64 %0, t; }"
        : "=r"(a) : "l"(p));
    return a;
}
__device__ __forceinline__ unsigned mapa_rank(unsigned laddr, unsigned rank) {
    unsigned r;
    asm("mapa.shared::cluster.u32 %0, %1, %2;" : "=r"(r) : "r"(laddr), "r"(rank));
    return r;
}
// remote push: cluster-scope relaxed (morally strong, b64 no-tear)
__device__ __forceinline__ void st_clu64(unsigned addr, unsigned long long v) {
    asm volatile("st.relaxed.cluster.shared::cluster.b64 [%0], %1;"
                 :: "r"(addr), "l"(v) : "memory");
}
// local mailbox read (R9-proven): cluster-scope relaxed load
__device__ __forceinline__ unsigned long long ld_clu64(unsigned addr) {
    unsigned long long v;
    asm volatile("ld.relaxed.cluster.shared.b64 %0, [%1];" : "=l"(v) : "r"(addr) : "memory");
    return v;
}
__device__ __forceinline__ float fast_sigmoid(float x) {
    return __fdividef(1.f, 1.f + __expf(-x));
}
__device__ __forceinline__ float fast_tanh(float x) {
    return 1.f - __fdividef(2.f, __expf(2.f * x) + 1.f);
}

// ---------------------------------------------------------------------------
// GEMM body (proven tile code): G[s][j] = feats[s].W_ih[j][0:1024] + bias[j]
// ---------------------------------------------------------------------------
__device__ void gemm_body(
    float* smem, int gb,
    const float* __restrict__ x, const float* __restrict__ hi,
    const float* __restrict__ W_ih,
    const float* __restrict__ b_ih, const float* __restrict__ b_hh)
{
    float (*As)[68] = (float(*)[68])smem;
    float (*Bs)[68] = (float(*)[68])(smem + 16 * 68);

    const int tid = threadIdx.x;
    const int bn  = gb & 15;
    const int bm  = gb >> 4;           // M tiles complete in s-order
    const int tx  = tid & 15;
    const int ty  = tid >> 4;

    const int lm  = tid >> 2;
    const int lk4 = (tid & 3) * 4;

    const int s  = bm * 64 + lm;
    const int t  = s >> 6, b = s & 63;
    const float* xrow  = &x [((size_t)(b * 128 + t)) << 9];
    const float* hirow = &hi[((size_t)(b * 128 + t)) << 9];
    const float* wrow  = &W_ih[(size_t)(bn * 64 + (tid >> 2)) * 1280];

    float acc[4][4] = {};

    for (int kt = 0; kt < 64; kt++) {
        const int kbase = kt * 16 + lk4;
        float4 av;
        if (kbase < 512) av = *(const float4*)&xrow[kbase];
        else             av = *(const float4*)&hirow[kbase - 512];
        As[lk4 + 0][lm] = av.x;
        As[lk4 + 1][lm] = av.y;
        As[lk4 + 2][lm] = av.z;
        As[lk4 + 3][lm] = av.w;
        float4 bv = *(const float4*)&wrow[kbase];
        Bs[lk4 + 0][tid >> 2] = bv.x;
        Bs[lk4 + 1][tid >> 2] = bv.y;
        Bs[lk4 + 2][tid >> 2] = bv.z;
        Bs[lk4 + 3][tid >> 2] = bv.w;
        __syncthreads();

#pragma unroll
        for (int kk = 0; kk < 16; kk++) {
            float ar[4], br[4];
#pragma unroll
            for (int i = 0; i < 4; i++) ar[i] = As[kk][ty * 4 + i];
#pragma unroll
            for (int j = 0; j < 4; j++) br[j] = Bs[kk][tx * 4 + j];
#pragma unroll
            for (int i = 0; i < 4; i++)
#pragma unroll
                for (int j = 0; j < 4; j++)
                    acc[i][j] = fmaf(ar[i], br[j], acc[i][j]);
        }
        __syncthreads();
    }

    const int col0 = bn * 64 + tx * 4;
    float bias[4];
#pragma unroll
    for (int j = 0; j < 4; j++) bias[j] = b_ih[col0 + j] + b_hh[col0 + j];
#pragma unroll
    for (int i = 0; i < 4; i++) {
        const size_t row = (size_t)(bm * 64 + ty * 4 + i);
        float4 v;
        v.x = acc[i][0] + bias[0];
        v.y = acc[i][1] + bias[1];
        v.z = acc[i][2] + bias[2];
        v.w = acc[i][3] + bias[3];
        *(float4*)&g_G[row * 1024 + col0] = v;
    }

    __threadfence();
    __syncthreads();
    if (tid == 0) atomicAdd(&g_gdone[bm], 1u);
}

// ---------------------------------------------------------------------------
// Chain body (R9-proven structure + R11 deltas): ONE cluster of 16 CTAs x
// 256 threads, no per-step barrier. CTA k owns h-indices 16k..16k+15;
// half-warp g2 of warp w owns jj = 16k+2w+g2; lane cg handles cols
// [16cg,16cg+16) of BOTH h and out_prev (64 FFMA2, packed register weights).
// Mailbox pair word = {h[2p+1] | h[2p]} with step stamp s&3 in h0's 2 LSBs.
// R11: (a) g_G loads double-buffered one step ahead (hides ~577cyc DRAM
// latency behind a full step), (b) DSMEM push precedes the g_H mirror store.
// ---------------------------------------------------------------------------
__device__ void chain_body(
    unsigned long long* mail, int k,
    const float* __restrict__ W_ih, const float* __restrict__ W_hh)
{
    const int tid  = threadIdx.x;
    const int warp = tid >> 5;
    const int lane = tid & 31;
    const int g2   = lane >> 4;
    const int cg   = lane & 15;

    const int jj = k * 16 + 2 * warp + g2;  // owned h-index

    // Register-resident packed weights: 4 gate rows x 8 col-pairs, h + out_prev
    unsigned long long wh[4][8], wo[4][8];
#pragma unroll
    for (int r = 0; r < 4; r++) {
        const float* whrow = &W_hh[(size_t)(jj + 256 * r) * 256];
        const float* worow = &W_ih[(size_t)(jj + 256 * r) * 1280 + 1024];
#pragma unroll
        for (int c = 0; c < 8; c++) {
            const int col = cg * 16 + 2 * c;
            wh[r][c] = pk2(whrow[col], whrow[col + 1]);
            wo[r][c] = pk2(worow[col], worow[col + 1]);
        }
    }

    // init mailbox: slot x gets stamp (x&3)^1 (never matches its first writer)
    for (int x = 0; x < MAIL_DEPTH; x++) {
        const unsigned long long iw = (unsigned long long)((x & 3) ^ 1);
        for (int i = tid; i < MAIL_SLOT; i += 256) mail[x * MAIL_SLOT + i] = iw;
    }

    const unsigned mail_base = smem_u32(mail);
    const unsigned rd_off    = (unsigned)(9 * cg) * 8u;          // my 8-pair group
    const unsigned push_off  = (unsigned)(9 * k + warp) * 8u;    // my pair word

    float c_state = 0.f;   // replicated per lane (bit-identical by construction)

    __syncthreads();
    // cluster barrier: all mailboxes initialized before any push
    asm volatile("barrier.cluster.arrive.aligned;" ::: "memory");
    asm volatile("barrier.cluster.wait.aligned;" ::: "memory");

    // prime G double-buffer for s=0 (gate on tile 0 first)
    while (ld_acq32(&g_gdone[0]) < 16u) { }
    float gpre[4];
#pragma unroll
    for (int r = 0; r < 4; r++) gpre[r] = __ldcg(&g_G[(size_t)jj + 256 * r]);

    int m = 0;  // s % 67
    for (int s = 0; s < NSTEPS; s++) {
        // ---- prefetch NEXT step's G rows (consumed one full step later)
        float gnext[4] = {0.f, 0.f, 0.f, 0.f};
        if (s + 1 < NSTEPS) {
            if (((s + 1) & 63) == 0) {
                while (ld_acq32(&g_gdone[(s + 1) >> 6]) < 16u) { }
            }
            const size_t gb = (size_t)(s + 1) * 1024 + jj;
#pragma unroll
            for (int r = 0; r < 4; r++) gnext[r] = __ldcg(&g_G[gb + 256 * r]);
        }

        unsigned long long acc[4] = {0ull, 0ull, 0ull, 0ull};

        // ---- out_prev phase: read h[s-64] pairs straight from the old slot
        if (s >= 64) {
            const int o_slot = (m + 3 >= MAIL_DEPTH) ? m + 3 - MAIL_DEPTH : m + 3;
            const unsigned oa = mail_base + (unsigned)(o_slot * MAIL_SLOT) * 8u + rd_off;
#pragma unroll
            for (int c = 0; c < 8; c++) {
                const unsigned long long v = ld_clu64(oa + c * 8);
#pragma unroll
                for (int r = 0; r < 4; r++) acc[r] = ffma2(wo[r][c], v, acc[r]);
            }
        }

        // ---- poll h[s-1]: 8 stamp-checked words, then FFMA2 on raw words
        if (s > 0) {
            const int h_slot = (m == 0) ? MAIL_DEPTH - 1 : m - 1;
            const unsigned ha = mail_base + (unsigned)(h_slot * MAIL_SLOT) * 8u + rd_off;
            const unsigned stamp = (unsigned)((s - 1) & 3);
            unsigned long long v[8];
            for (;;) {
                bool ok = true;
#pragma unroll
                for (int c = 0; c < 8; c++) {
                    v[c] = ld_clu64(ha + c * 8);
                    ok &= (((unsigned)v[c] & 3u) == stamp);
                }
                if (ok) break;
            }
#pragma unroll
            for (int c = 0; c < 8; c++) {
#pragma unroll
                for (int r = 0; r < 4; r++) acc[r] = ffma2(wh[r][c], v[c], acc[r]);
            }
        }

        // butterfly reduce over the 16 col-groups: ALL lanes get the sums
        float g4[4];
#pragma unroll
        for (int r = 0; r < 4; r++) {
            float lo, hi2;
            upk2(acc[r], lo, hi2);
            g4[r] = lo + hi2;
        }
#pragma unroll
        for (int off = 1; off < 16; off <<= 1) {
#pragma unroll
            for (int r = 0; r < 4; r++)
                g4[r] += __shfl_xor_sync(0xffffffffu, g4[r], off);
        }

        // gates: redundant across the half-warp, c_state replicated
        const float iv = fast_sigmoid(g4[0] + gpre[0]);
        const float fv = fast_sigmoid(g4[1] + gpre[1]);
        const float gv = fast_tanh  (g4[2] + gpre[2]);
        const float ov = fast_sigmoid(g4[3] + gpre[3]);
        c_state = fv * c_state + iv * gv;
        const float hv = ov * fast_tanh(c_state);

        // pair the halves and push FIRST (peers are waiting on this)
        const float partner = __shfl_xor_sync(0xffffffffu, hv, 16);
        if (lane < 16) {
            unsigned long long pw = pk2(hv, partner);            // {h1 | h0}
            pw = (pw & ~3ull) | (unsigned long long)(s & 3);     // stamp in h0 LSBs
            const unsigned la = mail_base + (unsigned)(m * MAIL_SLOT) * 8u + push_off;
            st_clu64(mapa_rank(la, (unsigned)lane), pw);
        }

        // exact mirror for fc (off the critical path, after the push)
        if (cg == 0) __stcg(&g_H[(size_t)s * 256 + jj], hv);

        // rotate G double-buffer
#pragma unroll
        for (int r = 0; r < 4; r++) gpre[r] = gnext[r];

        m = (m + 1 == MAIL_DEPTH) ? 0 : m + 1;
    }

    // cluster barrier before exit: peers' smem must outlive in-flight pushes
    asm volatile("barrier.cluster.arrive.aligned;" ::: "memory");
    asm volatile("barrier.cluster.wait.aligned;" ::: "memory");
}

// ---------------------------------------------------------------------------
// Fused kernel: blocks 0..15 = the chain cluster; 16..2063 = GEMM tiles.
// ---------------------------------------------------------------------------
__global__ void __launch_bounds__(256) fused_kernel(
    const float* __restrict__ x, const float* __restrict__ hi,
    const float* __restrict__ W_ih, const float* __restrict__ W_hh,
    const float* __restrict__ b_ih, const float* __restrict__ b_hh)
{
    extern __shared__ unsigned long long dynsmem[];
    if (blockIdx.x < CHAIN_CTAS) {
        chain_body(dynsmem, blockIdx.x, W_ih, W_hh);
    } else {
        gemm_body((float*)dynsmem, blockIdx.x - CHAIN_CTAS, x, hi, W_ih, b_ih, b_hh);
    }
}

// ---------------------------------------------------------------------------
// Kernel C: out[b][t][l] = H[s] . W_fc[l] + b_fc[l], s = t*64+b
// ---------------------------------------------------------------------------
__global__ void __launch_bounds__(128) fc_kernel(
    const float* __restrict__ W_fc, const float* __restrict__ b_fc,
    float* __restrict__ out)
{
    __shared__ float hrow[8][256];
    const int s0 = blockIdx.x * 8;
    const int l  = threadIdx.x;

#pragma unroll
    for (int ss = 0; ss < 8; ss++) {
        hrow[ss][l]       = g_H[(size_t)(s0 + ss) * 256 + l];
        hrow[ss][128 + l] = g_H[(size_t)(s0 + ss) * 256 + 128 + l];
    }
    __syncthreads();

    float acc[8];
    const float bias = b_fc[l];
#pragma unroll
    for (int ss = 0; ss < 8; ss++) acc[ss] = bias;

    const float* wr = &W_fc[(size_t)l * 256];
#pragma unroll 4
    for (int j = 0; j < 256; j++) {
        const float wv = wr[j];
#pragma unroll
        for (int ss = 0; ss < 8; ss++)
            acc[ss] = fmaf(wv, hrow[ss][j], acc[ss]);
    }

#pragma unroll
    for (int ss = 0; ss < 8; ss++) {
        const int s = s0 + ss;
        const int t = s >> 6, b = s & 63;
        out[((size_t)b << 14) + (size_t)t * 128 + l] = acc[ss];
    }
}

// ---------------------------------------------------------------------------
extern "C" void kernel_launch(void* const* d_in, const int* in_sizes, int n_in,
                              void* d_out, int out_size)
{
    const float* x    = (const float*)d_in[0];
    const float* hi   = (const float*)d_in[1];
    const float* W_ih = (const float*)d_in[2];
    const float* W_hh = (const float*)d_in[3];
    const float* b_ih = (const float*)d_in[4];
    const float* b_hh = (const float*)d_in[5];
    const float* W_fc = (const float*)d_in[6];
    const float* b_fc = (const float*)d_in[7];
    float* out = (float*)d_out;

    // clear tile counters every call/replay (mailbox init is in-kernel)
    void* gp = nullptr;
    cudaGetSymbolAddress(&gp, g_gdone);
    cudaMemsetAsync(gp, 0, 128 * sizeof(unsigned));

    const int smem_bytes = MAIL_DEPTH * MAIL_SLOT * sizeof(unsigned long long); // 77184
    cudaFuncSetAttribute(fused_kernel,
                         cudaFuncAttributeMaxDynamicSharedMemorySize, smem_bytes);
    cudaFuncSetAttribute(fused_kernel,
                         cudaFuncAttributeNonPortableClusterSizeAllowed, 1);

    cudaLaunchConfig_t cfg = {};
    cfg.gridDim  = dim3(CHAIN_CTAS + GEMM_BLOCKS, 1, 1);  // 2064 = 129 * 16
    cfg.blockDim = dim3(256, 1, 1);
    cfg.dynamicSmemBytes = smem_bytes;
    cudaLaunchAttribute attrs[1];
    attrs[0].id = cudaLaunchAttributeClusterDimension;
    attrs[0].val.clusterDim.x = 16;
    attrs[0].val.clusterDim.y = 1;
    attrs[0].val.clusterDim.z = 1;
    cfg.attrs = attrs;
    cfg.numAttrs = 1;
    cudaLaunchKernelEx(&cfg, fused_kernel, x, hi, W_ih, W_hh, b_ih, b_hh);

    fc_kernel<<<NSTEPS / 8, 128>>>(W_fc, b_fc, out);
}

// round 13
// speedup vs baseline: 1.0484x; 1.0195x over previous
#include <cuda_runtime.h>
#include <cuda_bf16.h>
#include <math.h>

// Problem dims: H=256, B=64, L=128, LABEL=128
// s = t*64 + b, S = 8192 sequential cells.

#define NSTEPS 8192
#define CHAIN_CTAS 16             // one 16-CTA cluster (non-portable size)
#define GEMM_BLOCKS 2048
#define MAIL_DEPTH 67             // odd, >=65 => structurally reuse-safe
#define MAIL_SLOT 144             // u64 words/slot: 16 groups * 9 (8 pairs + 1 pad)

// Scratch (device globals: allocation-free rule)
__device__ float    g_G[8192u * 1024u];  // 32 MB: input gates + bias
__device__ float    g_H[8192u * 256u];   // 8 MB: exact h history for fc
__device__ unsigned g_gdone[128];        // per-M-tile completion counters

// ---------------------------------------------------------------------------
// helpers
// ---------------------------------------------------------------------------
__device__ __forceinline__ unsigned ld_acq32(const unsigned* p) {
    unsigned v;
    asm volatile("ld.acquire.gpu.global.b32 %0, [%1];" : "=r"(v) : "l"(p) : "memory");
    return v;
}
__device__ __forceinline__ unsigned long long pk2(float lo, float hi) {
    unsigned long long r;
    asm("mov.b64 %0, {%1, %2};" : "=l"(r) : "f"(lo), "f"(hi));
    return r;
}
__device__ __forceinline__ void upk2(unsigned long long v, float& lo, float& hi) {
    asm("mov.b64 {%0, %1}, %2;" : "=f"(lo), "=f"(hi) : "l"(v));
}
__device__ __forceinline__ unsigned long long ffma2(
    unsigned long long a, unsigned long long b, unsigned long long c) {
    unsigned long long d;
    asm("fma.rn.f32x2 %0, %1, %2, %3;" : "=l"(d) : "l"(a), "l"(b), "l"(c));
    return d;
}
__device__ __forceinline__ unsigned smem_u32(const void* p) {
    unsigned a;
    asm("{ .reg .u64 t; cvta.to.shared.u64 t, %1; cvt.u32.u64 %0, t; }"
        : "=r"(a) : "l"(p));
    return a;
}
__device__ __forceinline__ unsigned mapa_rank(unsigned laddr, unsigned rank) {
    unsigned r;
    asm("mapa.shared::cluster.u32 %0, %1, %2;" : "=r"(r) : "r"(laddr), "r"(rank));
    return r;
}
// remote push: cluster-scope relaxed (morally strong, b64 no-tear)
__device__ __forceinline__ void st_clu64(unsigned addr, unsigned long long v) {
    asm volatile("st.relaxed.cluster.shared::cluster.b64 [%0], %1;"
                 :: "r"(addr), "l"(v) : "memory");
}
// local mailbox read (R9-proven): cluster-scope relaxed load
__device__ __forceinline__ unsigned long long ld_clu64(unsigned addr) {
    unsigned long long v;
    asm volatile("ld.relaxed.cluster.shared.b64 %0, [%1];" : "=l"(v) : "r"(addr) : "memory");
    return v;
}
__device__ __forceinline__ float fast_tanh(float x) {
    return 1.f - __fdividef(2.f, __expf(2.f * x) + 1.f);
}

// ---------------------------------------------------------------------------
// GEMM body (proven tile code): G[s][j] = feats[s].W_ih[j][0:1024] + bias[j]
// ---------------------------------------------------------------------------
__device__ void gemm_body(
    float* smem, int gb,
    const float* __restrict__ x, const float* __restrict__ hi,
    const float* __restrict__ W_ih,
    const float* __restrict__ b_ih, const float* __restrict__ b_hh)
{
    float (*As)[68] = (float(*)[68])smem;
    float (*Bs)[68] = (float(*)[68])(smem + 16 * 68);

    const int tid = threadIdx.x;
    const int bn  = gb & 15;
    const int bm  = gb >> 4;           // M tiles complete in s-order
    const int tx  = tid & 15;
    const int ty  = tid >> 4;

    const int lm  = tid >> 2;
    const int lk4 = (tid & 3) * 4;

    const int s  = bm * 64 + lm;
    const int t  = s >> 6, b = s & 63;
    const float* xrow  = &x [((size_t)(b * 128 + t)) << 9];
    const float* hirow = &hi[((size_t)(b * 128 + t)) << 9];
    const float* wrow  = &W_ih[(size_t)(bn * 64 + (tid >> 2)) * 1280];

    float acc[4][4] = {};

    for (int kt = 0; kt < 64; kt++) {
        const int kbase = kt * 16 + lk4;
        float4 av;
        if (kbase < 512) av = *(const float4*)&xrow[kbase];
        else             av = *(const float4*)&hirow[kbase - 512];
        As[lk4 + 0][lm] = av.x;
        As[lk4 + 1][lm] = av.y;
        As[lk4 + 2][lm] = av.z;
        As[lk4 + 3][lm] = av.w;
        float4 bv = *(const float4*)&wrow[kbase];
        Bs[lk4 + 0][tid >> 2] = bv.x;
        Bs[lk4 + 1][tid >> 2] = bv.y;
        Bs[lk4 + 2][tid >> 2] = bv.z;
        Bs[lk4 + 3][tid >> 2] = bv.w;
        __syncthreads();

#pragma unroll
        for (int kk = 0; kk < 16; kk++) {
            float ar[4], br[4];
#pragma unroll
            for (int i = 0; i < 4; i++) ar[i] = As[kk][ty * 4 + i];
#pragma unroll
            for (int j = 0; j < 4; j++) br[j] = Bs[kk][tx * 4 + j];
#pragma unroll
            for (int i = 0; i < 4; i++)
#pragma unroll
                for (int j = 0; j < 4; j++)
                    acc[i][j] = fmaf(ar[i], br[j], acc[i][j]);
        }
        __syncthreads();
    }

    const int col0 = bn * 64 + tx * 4;
    float bias[4];
#pragma unroll
    for (int j = 0; j < 4; j++) bias[j] = b_ih[col0 + j] + b_hh[col0 + j];
#pragma unroll
    for (int i = 0; i < 4; i++) {
        const size_t row = (size_t)(bm * 64 + ty * 4 + i);
        float4 v;
        v.x = acc[i][0] + bias[0];
        v.y = acc[i][1] + bias[1];
        v.z = acc[i][2] + bias[2];
        v.w = acc[i][3] + bias[3];
        *(float4*)&g_G[row * 1024 + col0] = v;
    }

    __threadfence();
    __syncthreads();
    if (tid == 0) atomicAdd(&g_gdone[bm], 1u);
}

// ---------------------------------------------------------------------------
// Chain body (R9-proven structure): ONE cluster of 16 CTAs x 256 threads,
// no per-step barrier. CTA k owns h-indices 16k..16k+15; half-warp g2 of
// warp w owns jj = 16k+2w+g2; lane cg handles cols [16cg,16cg+16) of BOTH
// h and out_prev (64 FFMA2, packed register weights).
// Mailbox pair word = {h[2p+1] | h[2p]} with step stamp s&3 in h0's 2 LSBs.
// R12 deltas vs R9:
//  (a) lane-parallel gates: lane cg computes nonlinearity r=cg&3 only
//      (uniform v = 1/(1+e^{k x}) form; sigmoid k=-1 -> v, tanh k=2 ->
//      1-2v), then 4 shfl_idx redistribute — MUFU warp-instrs 10 -> 4,
//      exact same EX2/RCP math.
//  (b) mapa hoisted out of the step loop (affine DSMEM aperture).
// ---------------------------------------------------------------------------
__device__ void chain_body(
    unsigned long long* mail, int k,
    const float* __restrict__ W_ih, const float* __restrict__ W_hh)
{
    const int tid  = threadIdx.x;
    const int warp = tid >> 5;
    const int lane = tid & 31;
    const int g2   = lane >> 4;
    const int cg   = lane & 15;

    const int jj = k * 16 + 2 * warp + g2;  // owned h-index

    // Register-resident packed weights: 4 gate rows x 8 col-pairs, h + out_prev
    unsigned long long wh[4][8], wo[4][8];
#pragma unroll
    for (int r = 0; r < 4; r++) {
        const float* whrow = &W_hh[(size_t)(jj + 256 * r) * 256];
        const float* worow = &W_ih[(size_t)(jj + 256 * r) * 1280 + 1024];
#pragma unroll
        for (int c = 0; c < 8; c++) {
            const int col = cg * 16 + 2 * c;
            wh[r][c] = pk2(whrow[col], whrow[col + 1]);
            wo[r][c] = pk2(worow[col], worow[col + 1]);
        }
    }

    // init mailbox: slot x gets stamp (x&3)^1 (never matches its first writer)
    for (int x = 0; x < MAIL_DEPTH; x++) {
        const unsigned long long iw = (unsigned long long)((x & 3) ^ 1);
        for (int i = tid; i < MAIL_SLOT; i += 256) mail[x * MAIL_SLOT + i] = iw;
    }

    const unsigned mail_base = smem_u32(mail);
    const unsigned rd_off    = (unsigned)(9 * cg) * 8u;          // my 8-pair group
    const unsigned push_off  = (unsigned)(9 * k + warp) * 8u;    // my pair word

    // hoisted mapa: per-rank push base (aperture is affine in local offset)
    unsigned push_base = 0;
    if (lane < 16)
        push_base = mapa_rank(mail_base + push_off, (unsigned)lane);

    float c_state = 0.f;   // replicated per lane (bit-identical by construction)

    __syncthreads();
    // cluster barrier: all mailboxes initialized before any push
    asm volatile("barrier.cluster.arrive.aligned;" ::: "memory");
    asm volatile("barrier.cluster.wait.aligned;" ::: "memory");

    int m = 0;  // s % 67
    for (int s = 0; s < NSTEPS; s++) {
        // G gating (once per 64 steps) + G prefetch
        if ((s & 63) == 0) {
            while (ld_acq32(&g_gdone[s >> 6]) < 16u) { }
        }
        float gpre[4];
        {
            const size_t gb = (size_t)s * 1024 + jj;
#pragma unroll
            for (int r = 0; r < 4; r++) gpre[r] = __ldcg(&g_G[gb + 256 * r]);
        }

        unsigned long long acc[4] = {0ull, 0ull, 0ull, 0ull};

        // ---- out_prev phase: read h[s-64] pairs straight from the old slot
        if (s >= 64) {
            const int o_slot = (m + 3 >= MAIL_DEPTH) ? m + 3 - MAIL_DEPTH : m + 3;
            const unsigned oa = mail_base + (unsigned)(o_slot * MAIL_SLOT) * 8u + rd_off;
#pragma unroll
            for (int c = 0; c < 8; c++) {
                const unsigned long long v = ld_clu64(oa + c * 8);
#pragma unroll
                for (int r = 0; r < 4; r++) acc[r] = ffma2(wo[r][c], v, acc[r]);
            }
        }

        // ---- poll h[s-1]: 8 stamp-checked words, then FFMA2 on raw words
        if (s > 0) {
            const int h_slot = (m == 0) ? MAIL_DEPTH - 1 : m - 1;
            const unsigned ha = mail_base + (unsigned)(h_slot * MAIL_SLOT) * 8u + rd_off;
            const unsigned stamp = (unsigned)((s - 1) & 3);
            unsigned long long v[8];
            for (;;) {
                bool ok = true;
#pragma unroll
                for (int c = 0; c < 8; c++) {
                    v[c] = ld_clu64(ha + c * 8);
                    ok &= (((unsigned)v[c] & 3u) == stamp);
                }
                if (ok) break;
            }
#pragma unroll
            for (int c = 0; c < 8; c++) {
#pragma unroll
                for (int r = 0; r < 4; r++) acc[r] = ffma2(wh[r][c], v[c], acc[r]);
            }
        }

        // butterfly reduce over the 16 col-groups: ALL lanes get the sums
        float g4[4];
#pragma unroll
        for (int r = 0; r < 4; r++) {
            float lo, hi2;
            upk2(acc[r], lo, hi2);
            g4[r] = lo + hi2;
        }
#pragma unroll
        for (int off = 1; off < 16; off <<= 1) {
#pragma unroll
            for (int r = 0; r < 4; r++)
                g4[r] += __shfl_xor_sync(0xffffffffu, g4[r], off);
        }

        // ---- lane-parallel gates (exact math, 4 MUFU/warp total) ----
        // lane handles gate r = cg&3: uniform v = 1/(1+e^{k x});
        // sigmoid (i,f,o): k=-1 -> v ; tanh (g): k=2 -> 1-2v.
        const float x0 = g4[0] + gpre[0];
        const float x1 = g4[1] + gpre[1];
        const float x2 = g4[2] + gpre[2];
        const float x3 = g4[3] + gpre[3];
        const int   r    = cg & 3;
        const float a01  = (r & 1) ? x1 : x0;
        const float a23  = (r & 1) ? x3 : x2;
        const float xa   = (r & 2) ? a23 : a01;
        const bool  isg  = (r == 2);
        const float u    = __expf(isg ? 2.f * xa : -xa);
        const float vnl  = __fdividef(1.f, 1.f + u);
        const float outr = isg ? fmaf(-2.f, vnl, 1.f) : vnl;
        const int   gb4  = lane & ~3;
        const float iv = __shfl_sync(0xffffffffu, outr, gb4 + 0);
        const float fv = __shfl_sync(0xffffffffu, outr, gb4 + 1);
        const float gv = __shfl_sync(0xffffffffu, outr, gb4 + 2);
        const float ov = __shfl_sync(0xffffffffu, outr, gb4 + 3);

        c_state = fv * c_state + iv * gv;
        const float hv = ov * fast_tanh(c_state);

        // exact mirror for fc (off the critical path)
        if (cg == 0) __stcg(&g_H[(size_t)s * 256 + jj], hv);

        // pair the halves and push: lanes 0..15 -> 16 cluster CTAs
        const float partner = __shfl_xor_sync(0xffffffffu, hv, 16);
        if (lane < 16) {
            unsigned long long pw = pk2(hv, partner);            // {h1 | h0}
            pw = (pw & ~3ull) | (unsigned long long)(s & 3);     // stamp in h0 LSBs
            st_clu64(push_base + (unsigned)(m * MAIL_SLOT) * 8u, pw);
        }

        m = (m + 1 == MAIL_DEPTH) ? 0 : m + 1;
    }

    // cluster barrier before exit: peers' smem must outlive in-flight pushes
    asm volatile("barrier.cluster.arrive.aligned;" ::: "memory");
    asm volatile("barrier.cluster.wait.aligned;" ::: "memory");
}

// ---------------------------------------------------------------------------
// Fused kernel: blocks 0..15 = the chain cluster; 16..2063 = GEMM tiles.
// ---------------------------------------------------------------------------
__global__ void __launch_bounds__(256) fused_kernel(
    const float* __restrict__ x, const float* __restrict__ hi,
    const float* __restrict__ W_ih, const float* __restrict__ W_hh,
    const float* __restrict__ b_ih, const float* __restrict__ b_hh)
{
    extern __shared__ unsigned long long dynsmem[];
    if (blockIdx.x < CHAIN_CTAS) {
        chain_body(dynsmem, blockIdx.x, W_ih, W_hh);
    } else {
        gemm_body((float*)dynsmem, blockIdx.x - CHAIN_CTAS, x, hi, W_ih, b_ih, b_hh);
    }
}

// ---------------------------------------------------------------------------
// Kernel C: out[b][t][l] = H[s] . W_fc[l] + b_fc[l], s = t*64+b
// ---------------------------------------------------------------------------
__global__ void __launch_bounds__(128) fc_kernel(
    const float* __restrict__ W_fc, const float* __restrict__ b_fc,
    float* __restrict__ out)
{
    __shared__ float hrow[8][256];
    const int s0 = blockIdx.x * 8;
    const int l  = threadIdx.x;

#pragma unroll
    for (int ss = 0; ss < 8; ss++) {
        hrow[ss][l]       = g_H[(size_t)(s0 + ss) * 256 + l];
        hrow[ss][128 + l] = g_H[(size_t)(s0 + ss) * 256 + 128 + l];
    }
    __syncthreads();

    float acc[8];
    const float bias = b_fc[l];
#pragma unroll
    for (int ss = 0; ss < 8; ss++) acc[ss] = bias;

    const float* wr = &W_fc[(size_t)l * 256];
#pragma unroll 4
    for (int j = 0; j < 256; j++) {
        const float wv = wr[j];
#pragma unroll
        for (int ss = 0; ss < 8; ss++)
            acc[ss] = fmaf(wv, hrow[ss][j], acc[ss]);
    }

#pragma unroll
    for (int ss = 0; ss < 8; ss++) {
        const int s = s0 + ss;
        const int t = s >> 6, b = s & 63;
        out[((size_t)b << 14) + (size_t)t * 128 + l] = acc[ss];
    }
}

// ---------------------------------------------------------------------------
extern "C" void kernel_launch(void* const* d_in, const int* in_sizes, int n_in,
                              void* d_out, int out_size)
{
    const float* x    = (const float*)d_in[0];
    const float* hi   = (const float*)d_in[1];
    const float* W_ih = (const float*)d_in[2];
    const float* W_hh = (const float*)d_in[3];
    const float* b_ih = (const float*)d_in[4];
    const float* b_hh = (const float*)d_in[5];
    const float* W_fc = (const float*)d_in[6];
    const float* b_fc = (const float*)d_in[7];
    float* out = (float*)d_out;

    // clear tile counters every call/replay (mailbox init is in-kernel)
    void* gp = nullptr;
    cudaGetSymbolAddress(&gp, g_gdone);
    cudaMemsetAsync(gp, 0, 128 * sizeof(unsigned));

    const int smem_bytes = MAIL_DEPTH * MAIL_SLOT * sizeof(unsigned long long); // 77184
    cudaFuncSetAttribute(fused_kernel,
                         cudaFuncAttributeMaxDynamicSharedMemorySize, smem_bytes);
    cudaFuncSetAttribute(fused_kernel,
                         cudaFuncAttributeNonPortableClusterSizeAllowed, 1);

    cudaLaunchConfig_t cfg = {};
    cfg.gridDim  = dim3(CHAIN_CTAS + GEMM_BLOCKS, 1, 1);  // 2064 = 129 * 16
    cfg.blockDim = dim3(256, 1, 1);
    cfg.dynamicSmemBytes = smem_bytes;
    cudaLaunchAttribute attrs[1];
    attrs[0].id = cudaLaunchAttributeClusterDimension;
    attrs[0].val.clusterDim.x = 16;
    attrs[0].val.clusterDim.y = 1;
    attrs[0].val.clusterDim.z = 1;
    cfg.attrs = attrs;
    cfg.numAttrs = 1;
    cudaLaunchKernelEx(&cfg, fused_kernel, x, hi, W_ih, W_hh, b_ih, b_hh);

    fc_kernel<<<NSTEPS / 8, 128>>>(W_fc, b_fc, out);
}

// round 15
// speedup vs baseline: 1.0647x; 1.0155x over previous
#include <cuda_runtime.h>
#include <cuda_bf16.h>
#include <math.h>

// Problem dims: H=256, B=64, L=128, LABEL=128
// s = t*64 + b, S = 8192 sequential cells.

#define NSTEPS 8192
#define CHAIN_CTAS 16             // one 16-CTA cluster (non-portable size)
#define GEMM_BLOCKS 2048
#define MAIL_DEPTH 67             // odd, >=65 => structurally reuse-safe
#define MAIL_SLOT 144             // u64 words/slot: 16 groups * 9 (8 pairs + 1 pad)

// Scratch (device globals: allocation-free rule)
__device__ float    g_G[8192u * 1024u];  // 32 MB: input gates + bias
__device__ float    g_H[8192u * 256u];   // 8 MB: exact h history for fc
__device__ unsigned g_gdone[128];        // per-M-tile completion counters

// ---------------------------------------------------------------------------
// helpers
// ---------------------------------------------------------------------------
__device__ __forceinline__ unsigned ld_acq32(const unsigned* p) {
    unsigned v;
    asm volatile("ld.acquire.gpu.global.b32 %0, [%1];" : "=r"(v) : "l"(p) : "memory");
    return v;
}
__device__ __forceinline__ unsigned long long pk2(float lo, float hi) {
    unsigned long long r;
    asm("mov.b64 %0, {%1, %2};" : "=l"(r) : "f"(lo), "f"(hi));
    return r;
}
__device__ __forceinline__ void upk2(unsigned long long v, float& lo, float& hi) {
    asm("mov.b64 {%0, %1}, %2;" : "=f"(lo), "=f"(hi) : "l"(v));
}
__device__ __forceinline__ unsigned long long ffma2(
    unsigned long long a, unsigned long long b, unsigned long long c) {
    unsigned long long d;
    asm("fma.rn.f32x2 %0, %1, %2, %3;" : "=l"(d) : "l"(a), "l"(b), "l"(c));
    return d;
}
__device__ __forceinline__ unsigned smem_u32(const void* p) {
    unsigned a;
    asm("{ .reg .u64 t; cvta.to.shared.u64 t, %1; cvt.u32.u64 %0, t; }"
        : "=r"(a) : "l"(p));
    return a;
}
__device__ __forceinline__ unsigned mapa_rank(unsigned laddr, unsigned rank) {
    unsigned r;
    asm("mapa.shared::cluster.u32 %0, %1, %2;" : "=r"(r) : "r"(laddr), "r"(rank));
    return r;
}
// remote push: 32-bit cluster-scope relaxed store (value+stamp in ONE word)
__device__ __forceinline__ void st_clu32(unsigned addr, unsigned v) {
    asm volatile("st.relaxed.cluster.shared::cluster.b32 [%0], %1;"
                 :: "r"(addr), "r"(v) : "memory");
}
// local mailbox read (R9-proven scope): cluster-scope relaxed b64 load —
// morally strong w.r.t. the remote cluster-scope stores (visibility
// guaranteed; the R13 cta-scope read was not).
__device__ __forceinline__ unsigned long long ld_clu64(unsigned addr) {
    unsigned long long v;
    asm volatile("ld.relaxed.cluster.shared.b64 %0, [%1];" : "=l"(v) : "r"(addr) : "memory");
    return v;
}
__device__ __forceinline__ float fast_sigmoid(float x) {
    return __fdividef(1.f, 1.f + __expf(-x));
}
__device__ __forceinline__ float fast_tanh(float x) {
    return 1.f - __fdividef(2.f, __expf(2.f * x) + 1.f);
}

// ---------------------------------------------------------------------------
// GEMM body (proven tile code): G[s][j] = feats[s].W_ih[j][0:1024] + bias[j]
// ---------------------------------------------------------------------------
__device__ void gemm_body(
    float* smem, int gb,
    const float* __restrict__ x, const float* __restrict__ hi,
    const float* __restrict__ W_ih,
    const float* __restrict__ b_ih, const float* __restrict__ b_hh)
{
    float (*As)[68] = (float(*)[68])smem;
    float (*Bs)[68] = (float(*)[68])(smem + 16 * 68);

    const int tid = threadIdx.x;
    const int bn  = gb & 15;
    const int bm  = gb >> 4;           // M tiles complete in s-order
    const int tx  = tid & 15;
    const int ty  = tid >> 4;

    const int lm  = tid >> 2;
    const int lk4 = (tid & 3) * 4;

    const int s  = bm * 64 + lm;
    const int t  = s >> 6, b = s & 63;
    const float* xrow  = &x [((size_t)(b * 128 + t)) << 9];
    const float* hirow = &hi[((size_t)(b * 128 + t)) << 9];
    const float* wrow  = &W_ih[(size_t)(bn * 64 + (tid >> 2)) * 1280];

    float acc[4][4] = {};

    for (int kt = 0; kt < 64; kt++) {
        const int kbase = kt * 16 + lk4;
        float4 av;
        if (kbase < 512) av = *(const float4*)&xrow[kbase];
        else             av = *(const float4*)&hirow[kbase - 512];
        As[lk4 + 0][lm] = av.x;
        As[lk4 + 1][lm] = av.y;
        As[lk4 + 2][lm] = av.z;
        As[lk4 + 3][lm] = av.w;
        float4 bv = *(const float4*)&wrow[kbase];
        Bs[lk4 + 0][tid >> 2] = bv.x;
        Bs[lk4 + 1][tid >> 2] = bv.y;
        Bs[lk4 + 2][tid >> 2] = bv.z;
        Bs[lk4 + 3][tid >> 2] = bv.w;
        __syncthreads();

#pragma unroll
        for (int kk = 0; kk < 16; kk++) {
            float ar[4], br[4];
#pragma unroll
            for (int i = 0; i < 4; i++) ar[i] = As[kk][ty * 4 + i];
#pragma unroll
            for (int j = 0; j < 4; j++) br[j] = Bs[kk][tx * 4 + j];
#pragma unroll
            for (int i = 0; i < 4; i++)
#pragma unroll
                for (int j = 0; j < 4; j++)
                    acc[i][j] = fmaf(ar[i], br[j], acc[i][j]);
        }
        __syncthreads();
    }

    const int col0 = bn * 64 + tx * 4;
    float bias[4];
#pragma unroll
    for (int j = 0; j < 4; j++) bias[j] = b_ih[col0 + j] + b_hh[col0 + j];
#pragma unroll
    for (int i = 0; i < 4; i++) {
        const size_t row = (size_t)(bm * 64 + ty * 4 + i);
        float4 v;
        v.x = acc[i][0] + bias[0];
        v.y = acc[i][1] + bias[1];
        v.z = acc[i][2] + bias[2];
        v.w = acc[i][3] + bias[3];
        *(float4*)&g_G[row * 1024 + col0] = v;
    }

    __threadfence();
    __syncthreads();
    if (tid == 0) atomicAdd(&g_gdone[bm], 1u);
}

// ---------------------------------------------------------------------------
// Chain body (R9-proven reads/geometry): ONE cluster of 16 CTAs x 256
// threads, no per-step barrier. CTA k owns h-indices 16k..16k+15;
// half-warp g2 of warp w owns jj = 16k+2w+g2; lane cg handles cols
// [16cg,16cg+16) of BOTH h and out_prev (64 FFMA2, packed register weights).
// R14 handshake: the 64-bit pair word {h_odd | h_even} is written as TWO
// independent 32-bit cluster stores (one per half-warp; no partner shuffle),
// each word self-stamped with s&3 in its 2 mantissa LSBs. Consumers keep
// R9's ld.relaxed.cluster.b64 reads (morally strong vs the remote stores);
// poll checks BOTH halves' stamps, so half-landed pairs simply retry.
// out_prev slot is 64 steps old (both halves long landed) -> uncheckd read.
// Slot reuse at s+67 transitively requires our s+66 publish -> ABA-safe;
// old-generation stamps differ by +1 mod 4 -> never falsely match.
// ---------------------------------------------------------------------------
__device__ void chain_body(
    unsigned long long* mail, int k,
    const float* __restrict__ W_ih, const float* __restrict__ W_hh)
{
    const int tid  = threadIdx.x;
    const int warp = tid >> 5;
    const int lane = tid & 31;
    const int g2   = lane >> 4;
    const int cg   = lane & 15;

    const int jj = k * 16 + 2 * warp + g2;  // owned h-index

    // Register-resident packed weights: 4 gate rows x 8 col-pairs, h + out_prev
    unsigned long long wh[4][8], wo[4][8];
#pragma unroll
    for (int r = 0; r < 4; r++) {
        const float* whrow = &W_hh[(size_t)(jj + 256 * r) * 256];
        const float* worow = &W_ih[(size_t)(jj + 256 * r) * 1280 + 1024];
#pragma unroll
        for (int c = 0; c < 8; c++) {
            const int col = cg * 16 + 2 * c;
            wh[r][c] = pk2(whrow[col], whrow[col + 1]);
            wo[r][c] = pk2(worow[col], worow[col + 1]);
        }
    }

    // init mailbox: slot x gets stamp (x&3)^1 in BOTH 32-bit halves
    for (int x = 0; x < MAIL_DEPTH; x++) {
        const unsigned long long iw =
            (unsigned long long)((x & 3) ^ 1) * 0x100000001ull;
        for (int i = tid; i < MAIL_SLOT; i += 256) mail[x * MAIL_SLOT + i] = iw;
    }

    const unsigned mail_base = smem_u32(mail);
    const unsigned rd_off    = (unsigned)(9 * cg) * 8u;   // my 8-pair group
    // my 32-bit half-word: group k, pair word warp, half g2; pushed to rank cg
    const unsigned push_base =
        mapa_rank(mail_base + (unsigned)((9 * k + warp) * 8 + 4 * g2),
                  (unsigned)cg);

    float c_state = 0.f;   // replicated per lane (bit-identical by construction)

    __syncthreads();
    // cluster barrier: all mailboxes initialized before any push
    asm volatile("barrier.cluster.arrive.aligned;" ::: "memory");
    asm volatile("barrier.cluster.wait.aligned;" ::: "memory");

    int m = 0;  // s % 67
    for (int s = 0; s < NSTEPS; s++) {
        // G gating (once per 64 steps) + G prefetch
        if ((s & 63) == 0) {
            while (ld_acq32(&g_gdone[s >> 6]) < 16u) { }
        }
        float gpre[4];
        {
            const size_t gb = (size_t)s * 1024 + jj;
#pragma unroll
            for (int r = 0; r < 4; r++) gpre[r] = __ldcg(&g_G[gb + 256 * r]);
        }

        unsigned long long acc[4] = {0ull, 0ull, 0ull, 0ull};

        // ---- out_prev phase: read h[s-64] pairs straight from the old slot
        if (s >= 64) {
            const int o_slot = (m + 3 >= MAIL_DEPTH) ? m + 3 - MAIL_DEPTH : m + 3;
            const unsigned oa = mail_base + (unsigned)(o_slot * MAIL_SLOT) * 8u + rd_off;
#pragma unroll
            for (int c = 0; c < 8; c++) {
                const unsigned long long v = ld_clu64(oa + c * 8);
#pragma unroll
                for (int r = 0; r < 4; r++) acc[r] = ffma2(wo[r][c], v, acc[r]);
            }
        }

        // ---- poll h[s-1]: 8 b64 words, BOTH halves stamp-checked
        if (s > 0) {
            const int h_slot = (m == 0) ? MAIL_DEPTH - 1 : m - 1;
            const unsigned ha = mail_base + (unsigned)(h_slot * MAIL_SLOT) * 8u + rd_off;
            const unsigned long long stamp2 =
                (unsigned long long)((s - 1) & 3) * 0x100000001ull;
            unsigned long long v[8];
            for (;;) {
                unsigned long long diff = 0ull;
#pragma unroll
                for (int c = 0; c < 8; c++) {
                    v[c] = ld_clu64(ha + c * 8);
                    diff |= (v[c] ^ stamp2);
                }
                if ((diff & 0x0000000300000003ull) == 0ull) break;
            }
#pragma unroll
            for (int c = 0; c < 8; c++) {
#pragma unroll
                for (int r = 0; r < 4; r++) acc[r] = ffma2(wh[r][c], v[c], acc[r]);
            }
        }

        // butterfly reduce over the 16 col-groups: ALL lanes get the sums
        float g4[4];
#pragma unroll
        for (int r = 0; r < 4; r++) {
            float lo, hi2;
            upk2(acc[r], lo, hi2);
            g4[r] = lo + hi2;
        }
#pragma unroll
        for (int off = 1; off < 16; off <<= 1) {
#pragma unroll
            for (int r = 0; r < 4; r++)
                g4[r] += __shfl_xor_sync(0xffffffffu, g4[r], off);
        }

        // gates: redundant across the half-warp (R9-proven), c_state replicated
        const float iv = fast_sigmoid(g4[0] + gpre[0]);
        const float fv = fast_sigmoid(g4[1] + gpre[1]);
        const float gv = fast_tanh  (g4[2] + gpre[2]);
        const float ov = fast_sigmoid(g4[3] + gpre[3]);
        c_state = fv * c_state + iv * gv;
        const float hv = ov * fast_tanh(c_state);

        // push FIRST: every lane stores its jj's stamped 32-bit half to rank cg
        const unsigned pv = (__float_as_uint(hv) & ~3u) | (unsigned)(s & 3);
        st_clu32(push_base + (unsigned)(m * MAIL_SLOT) * 8u, pv);

        // exact mirror for fc (off the critical path)
        if (cg == 0) __stcg(&g_H[(size_t)s * 256 + jj], hv);

        m = (m + 1 == MAIL_DEPTH) ? 0 : m + 1;
    }

    // cluster barrier before exit: peers' smem must outlive in-flight pushes
    asm volatile("barrier.cluster.arrive.aligned;" ::: "memory");
    asm volatile("barrier.cluster.wait.aligned;" ::: "memory");
}

// ---------------------------------------------------------------------------
// Fused kernel: blocks 0..15 = the chain cluster; 16..2063 = GEMM tiles.
// ---------------------------------------------------------------------------
__global__ void __launch_bounds__(256) fused_kernel(
    const float* __restrict__ x, const float* __restrict__ hi,
    const float* __restrict__ W_ih, const float* __restrict__ W_hh,
    const float* __restrict__ b_ih, const float* __restrict__ b_hh)
{
    extern __shared__ unsigned long long dynsmem[];
    if (blockIdx.x < CHAIN_CTAS) {
        chain_body(dynsmem, blockIdx.x, W_ih, W_hh);
    } else {
        gemm_body((float*)dynsmem, blockIdx.x - CHAIN_CTAS, x, hi, W_ih, b_ih, b_hh);
    }
}

// ---------------------------------------------------------------------------
// Kernel C: out[b][t][l] = H[s] . W_fc[l] + b_fc[l], s = t*64+b
// ---------------------------------------------------------------------------
__global__ void __launch_bounds__(128) fc_kernel(
    const float* __restrict__ W_fc, const float* __restrict__ b_fc,
    float* __restrict__ out)
{
    __shared__ float hrow[8][256];
    const int s0 = blockIdx.x * 8;
    const int l  = threadIdx.x;

#pragma unroll
    for (int ss = 0; ss < 8; ss++) {
        hrow[ss][l]       = g_H[(size_t)(s0 + ss) * 256 + l];
        hrow[ss][128 + l] = g_H[(size_t)(s0 + ss) * 256 + 128 + l];
    }
    __syncthreads();

    float acc[8];
    const float bias = b_fc[l];
#pragma unroll
    for (int ss = 0; ss < 8; ss++) acc[ss] = bias;

    const float* wr = &W_fc[(size_t)l * 256];
#pragma unroll 4
    for (int j = 0; j < 256; j++) {
        const float wv = wr[j];
#pragma unroll
        for (int ss = 0; ss < 8; ss++)
            acc[ss] = fmaf(wv, hrow[ss][j], acc[ss]);
    }

#pragma unroll
    for (int ss = 0; ss < 8; ss++) {
        const int s = s0 + ss;
        const int t = s >> 6, b = s & 63;
        out[((size_t)b << 14) + (size_t)t * 128 + l] = acc[ss];
    }
}

// ---------------------------------------------------------------------------
extern "C" void kernel_launch(void* const* d_in, const int* in_sizes, int n_in,
                              void* d_out, int out_size)
{
    const float* x    = (const float*)d_in[0];
    const float* hi   = (const float*)d_in[1];
    const float* W_ih = (const float*)d_in[2];
    const float* W_hh = (const float*)d_in[3];
    const float* b_ih = (const float*)d_in[4];
    const float* b_hh = (const float*)d_in[5];
    const float* W_fc = (const float*)d_in[6];
    const float* b_fc = (const float*)d_in[7];
    float* out = (float*)d_out;

    // clear tile counters every call/replay (mailbox init is in-kernel)
    void* gp = nullptr;
    cudaGetSymbolAddress(&gp, g_gdone);
    cudaMemsetAsync(gp, 0, 128 * sizeof(unsigned));

    const int smem_bytes = MAIL_DEPTH * MAIL_SLOT * sizeof(unsigned long long); // 77184
    cudaFuncSetAttribute(fused_kernel,
                         cudaFuncAttributeMaxDynamicSharedMemorySize, smem_bytes);
    cudaFuncSetAttribute(fused_kernel,
                         cudaFuncAttributeNonPortableClusterSizeAllowed, 1);

    cudaLaunchConfig_t cfg = {};
    cfg.gridDim  = dim3(CHAIN_CTAS + GEMM_BLOCKS, 1, 1);  // 2064 = 129 * 16
    cfg.blockDim = dim3(256, 1, 1);
    cfg.dynamicSmemBytes = smem_bytes;
    cudaLaunchAttribute attrs[1];
    attrs[0].id = cudaLaunchAttributeClusterDimension;
    attrs[0].val.clusterDim.x = 16;
    attrs[0].val.clusterDim.y = 1;
    attrs[0].val.clusterDim.z = 1;
    cfg.attrs = attrs;
    cfg.numAttrs = 1;
    cudaLaunchKernelEx(&cfg, fused_kernel, x, hi, W_ih, W_hh, b_ih, b_hh);

    fc_kernel<<<NSTEPS / 8, 128>>>(W_fc, b_fc, out);
}

// round 16
// speedup vs baseline: 1.0677x; 1.0028x over previous
#include <cuda_runtime.h>
#include <cuda_bf16.h>
#include <math.h>

// Problem dims: H=256, B=64, L=128, LABEL=128
// s = t*64 + b, S = 8192 sequential cells.

#define NSTEPS 8192
#define CHAIN_CTAS 16             // one 16-CTA cluster (non-portable size)
#define GEMM_BLOCKS 2048
#define FC_BLOCKS   1024          // 8 steps per block
#define MAIL_DEPTH 67             // odd, >=65 => structurally reuse-safe
#define MAIL_SLOT 144             // u64 words/slot: 16 groups * 9 (8 pairs + 1 pad)

// Scratch (device globals: allocation-free rule)
__device__ float    g_G[8192u * 1024u];  // 32 MB: input gates + bias
__device__ unsigned g_Hs[8192u * 256u];  // 8 MB: stamped h mirror for fc
__device__ unsigned g_gdone[128];        // per-M-tile completion counters

// ---------------------------------------------------------------------------
// helpers
// ---------------------------------------------------------------------------
__device__ __forceinline__ unsigned ld_acq32(const unsigned* p) {
    unsigned v;
    asm volatile("ld.acquire.gpu.global.b32 %0, [%1];" : "=r"(v) : "l"(p) : "memory");
    return v;
}
__device__ __forceinline__ unsigned long long pk2(float lo, float hi) {
    unsigned long long r;
    asm("mov.b64 %0, {%1, %2};" : "=l"(r) : "f"(lo), "f"(hi));
    return r;
}
__device__ __forceinline__ void upk2(unsigned long long v, float& lo, float& hi) {
    asm("mov.b64 {%0, %1}, %2;" : "=f"(lo), "=f"(hi) : "l"(v));
}
__device__ __forceinline__ unsigned long long ffma2(
    unsigned long long a, unsigned long long b, unsigned long long c) {
    unsigned long long d;
    asm("fma.rn.f32x2 %0, %1, %2, %3;" : "=l"(d) : "l"(a), "l"(b), "l"(c));
    return d;
}
__device__ __forceinline__ unsigned smem_u32(const void* p) {
    unsigned a;
    asm("{ .reg .u64 t; cvta.to.shared.u64 t, %1; cvt.u32.u64 %0, t; }"
        : "=r"(a) : "l"(p));
    return a;
}
__device__ __forceinline__ unsigned mapa_rank(unsigned laddr, unsigned rank) {
    unsigned r;
    asm("mapa.shared::cluster.u32 %0, %1, %2;" : "=r"(r) : "r"(laddr), "r"(rank));
    return r;
}
// remote push: 32-bit cluster-scope relaxed store (value+stamp in ONE word)
__device__ __forceinline__ void st_clu32(unsigned addr, unsigned v) {
    asm volatile("st.relaxed.cluster.shared::cluster.b32 [%0], %1;"
                 :: "r"(addr), "r"(v) : "memory");
}
// local mailbox read (R9/R14-proven scope): cluster-scope relaxed b64 load
__device__ __forceinline__ unsigned long long ld_clu64(unsigned addr) {
    unsigned long long v;
    asm volatile("ld.relaxed.cluster.shared.b64 %0, [%1];" : "=l"(v) : "r"(addr) : "memory");
    return v;
}
// stamped global h mirror: relaxed 32-bit store / load (morally strong pair)
__device__ __forceinline__ void st_rlx32g(unsigned* p, unsigned v) {
    asm volatile("st.relaxed.gpu.global.b32 [%0], %1;" :: "l"(p), "r"(v) : "memory");
}
__device__ __forceinline__ unsigned ld_rlx32g(const unsigned* p) {
    unsigned v;
    asm volatile("ld.relaxed.gpu.global.b32 %0, [%1];" : "=r"(v) : "l"(p) : "memory");
    return v;
}
__device__ __forceinline__ float fast_sigmoid(float x) {
    return __fdividef(1.f, 1.f + __expf(-x));
}
__device__ __forceinline__ float fast_tanh(float x) {
    return 1.f - __fdividef(2.f, __expf(2.f * x) + 1.f);
}

// ---------------------------------------------------------------------------
// GEMM body (proven tile code): G[s][j] = feats[s].W_ih[j][0:1024] + bias[j]
// ---------------------------------------------------------------------------
__device__ void gemm_body(
    float* smem, int gb,
    const float* __restrict__ x, const float* __restrict__ hi,
    const float* __restrict__ W_ih,
    const float* __restrict__ b_ih, const float* __restrict__ b_hh)
{
    float (*As)[68] = (float(*)[68])smem;
    float (*Bs)[68] = (float(*)[68])(smem + 16 * 68);

    const int tid = threadIdx.x;
    const int bn  = gb & 15;
    const int bm  = gb >> 4;           // M tiles complete in s-order
    const int tx  = tid & 15;
    const int ty  = tid >> 4;

    const int lm  = tid >> 2;
    const int lk4 = (tid & 3) * 4;

    const int s  = bm * 64 + lm;
    const int t  = s >> 6, b = s & 63;
    const float* xrow  = &x [((size_t)(b * 128 + t)) << 9];
    const float* hirow = &hi[((size_t)(b * 128 + t)) << 9];
    const float* wrow  = &W_ih[(size_t)(bn * 64 + (tid >> 2)) * 1280];

    float acc[4][4] = {};

    for (int kt = 0; kt < 64; kt++) {
        const int kbase = kt * 16 + lk4;
        float4 av;
        if (kbase < 512) av = *(const float4*)&xrow[kbase];
        else             av = *(const float4*)&hirow[kbase - 512];
        As[lk4 + 0][lm] = av.x;
        As[lk4 + 1][lm] = av.y;
        As[lk4 + 2][lm] = av.z;
        As[lk4 + 3][lm] = av.w;
        float4 bv = *(const float4*)&wrow[kbase];
        Bs[lk4 + 0][tid >> 2] = bv.x;
        Bs[lk4 + 1][tid >> 2] = bv.y;
        Bs[lk4 + 2][tid >> 2] = bv.z;
        Bs[lk4 + 3][tid >> 2] = bv.w;
        __syncthreads();

#pragma unroll
        for (int kk = 0; kk < 16; kk++) {
            float ar[4], br[4];
#pragma unroll
            for (int i = 0; i < 4; i++) ar[i] = As[kk][ty * 4 + i];
#pragma unroll
            for (int j = 0; j < 4; j++) br[j] = Bs[kk][tx * 4 + j];
#pragma unroll
            for (int i = 0; i < 4; i++)
#pragma unroll
                for (int j = 0; j < 4; j++)
                    acc[i][j] = fmaf(ar[i], br[j], acc[i][j]);
        }
        __syncthreads();
    }

    const int col0 = bn * 64 + tx * 4;
    float bias[4];
#pragma unroll
    for (int j = 0; j < 4; j++) bias[j] = b_ih[col0 + j] + b_hh[col0 + j];
#pragma unroll
    for (int i = 0; i < 4; i++) {
        const size_t row = (size_t)(bm * 64 + ty * 4 + i);
        float4 v;
        v.x = acc[i][0] + bias[0];
        v.y = acc[i][1] + bias[1];
        v.z = acc[i][2] + bias[2];
        v.w = acc[i][3] + bias[3];
        *(float4*)&g_G[row * 1024 + col0] = v;
    }

    __threadfence();
    __syncthreads();
    if (tid == 0) atomicAdd(&g_gdone[bm], 1u);
}

// ---------------------------------------------------------------------------
// Chain body (R14-proven, verbatim except the stamped g_Hs mirror store):
// ONE cluster of 16 CTAs x 256 threads, no per-step barrier. CTA k owns
// h-indices 16k..16k+15; half-warp g2 of warp w owns jj = 16k+2w+g2; lane
// cg handles cols [16cg,16cg+16) of BOTH h and out_prev (64 FFMA2, packed
// register weights). 64-bit pair word written as TWO independent 32-bit
// cluster stores (no partner shuffle), each self-stamped with s&3 in its 2
// mantissa LSBs; consumers read ld.relaxed.cluster.b64 (morally strong) and
// stamp-check both halves. out_prev slot is 64 steps old -> unchecked read.
// ---------------------------------------------------------------------------
__device__ void chain_body(
    unsigned long long* mail, int k,
    const float* __restrict__ W_ih, const float* __restrict__ W_hh)
{
    const int tid  = threadIdx.x;
    const int warp = tid >> 5;
    const int lane = tid & 31;
    const int g2   = lane >> 4;
    const int cg   = lane & 15;

    const int jj = k * 16 + 2 * warp + g2;  // owned h-index

    // Register-resident packed weights: 4 gate rows x 8 col-pairs, h + out_prev
    unsigned long long wh[4][8], wo[4][8];
#pragma unroll
    for (int r = 0; r < 4; r++) {
        const float* whrow = &W_hh[(size_t)(jj + 256 * r) * 256];
        const float* worow = &W_ih[(size_t)(jj + 256 * r) * 1280 + 1024];
#pragma unroll
        for (int c = 0; c < 8; c++) {
            const int col = cg * 16 + 2 * c;
            wh[r][c] = pk2(whrow[col], whrow[col + 1]);
            wo[r][c] = pk2(worow[col], worow[col + 1]);
        }
    }

    // init mailbox: slot x gets stamp (x&3)^1 in BOTH 32-bit halves
    for (int x = 0; x < MAIL_DEPTH; x++) {
        const unsigned long long iw =
            (unsigned long long)((x & 3) ^ 1) * 0x100000001ull;
        for (int i = tid; i < MAIL_SLOT; i += 256) mail[x * MAIL_SLOT + i] = iw;
    }

    const unsigned mail_base = smem_u32(mail);
    const unsigned rd_off    = (unsigned)(9 * cg) * 8u;   // my 8-pair group
    // my 32-bit half-word: group k, pair word warp, half g2; pushed to rank cg
    const unsigned push_base =
        mapa_rank(mail_base + (unsigned)((9 * k + warp) * 8 + 4 * g2),
                  (unsigned)cg);

    float c_state = 0.f;   // replicated per lane (bit-identical by construction)

    __syncthreads();
    // cluster barrier: all mailboxes initialized before any push
    asm volatile("barrier.cluster.arrive.aligned;" ::: "memory");
    asm volatile("barrier.cluster.wait.aligned;" ::: "memory");

    int m = 0;  // s % 67
    for (int s = 0; s < NSTEPS; s++) {
        // G gating (once per 64 steps) + G prefetch
        if ((s & 63) == 0) {
            while (ld_acq32(&g_gdone[s >> 6]) < 16u) { }
        }
        float gpre[4];
        {
            const size_t gb = (size_t)s * 1024 + jj;
#pragma unroll
            for (int r = 0; r < 4; r++) gpre[r] = __ldcg(&g_G[gb + 256 * r]);
        }

        unsigned long long acc[4] = {0ull, 0ull, 0ull, 0ull};

        // ---- out_prev phase: read h[s-64] pairs straight from the old slot
        if (s >= 64) {
            const int o_slot = (m + 3 >= MAIL_DEPTH) ? m + 3 - MAIL_DEPTH : m + 3;
            const unsigned oa = mail_base + (unsigned)(o_slot * MAIL_SLOT) * 8u + rd_off;
#pragma unroll
            for (int c = 0; c < 8; c++) {
                const unsigned long long v = ld_clu64(oa + c * 8);
#pragma unroll
                for (int r = 0; r < 4; r++) acc[r] = ffma2(wo[r][c], v, acc[r]);
            }
        }

        // ---- poll h[s-1]: 8 b64 words, BOTH halves stamp-checked
        if (s > 0) {
            const int h_slot = (m == 0) ? MAIL_DEPTH - 1 : m - 1;
            const unsigned ha = mail_base + (unsigned)(h_slot * MAIL_SLOT) * 8u + rd_off;
            const unsigned long long stamp2 =
                (unsigned long long)((s - 1) & 3) * 0x100000001ull;
            unsigned long long v[8];
            for (;;) {
                unsigned long long diff = 0ull;
#pragma unroll
                for (int c = 0; c < 8; c++) {
                    v[c] = ld_clu64(ha + c * 8);
                    diff |= (v[c] ^ stamp2);
                }
                if ((diff & 0x0000000300000003ull) == 0ull) break;
            }
#pragma unroll
            for (int c = 0; c < 8; c++) {
#pragma unroll
                for (int r = 0; r < 4; r++) acc[r] = ffma2(wh[r][c], v[c], acc[r]);
            }
        }

        // butterfly reduce over the 16 col-groups: ALL lanes get the sums
        float g4[4];
#pragma unroll
        for (int r = 0; r < 4; r++) {
            float lo, hi2;
            upk2(acc[r], lo, hi2);
            g4[r] = lo + hi2;
        }
#pragma unroll
        for (int off = 1; off < 16; off <<= 1) {
#pragma unroll
            for (int r = 0; r < 4; r++)
                g4[r] += __shfl_xor_sync(0xffffffffu, g4[r], off);
        }

        // gates: redundant across the half-warp, c_state replicated
        const float iv = fast_sigmoid(g4[0] + gpre[0]);
        const float fv = fast_sigmoid(g4[1] + gpre[1]);
        const float gv = fast_tanh  (g4[2] + gpre[2]);
        const float ov = fast_sigmoid(g4[3] + gpre[3]);
        c_state = fv * c_state + iv * gv;
        const float hv = ov * fast_tanh(c_state);

        // push FIRST: every lane stores its jj's stamped 32-bit half to rank cg
        const unsigned pv = (__float_as_uint(hv) & ~3u) | (unsigned)(s & 3);
        st_clu32(push_base + (unsigned)(m * MAIL_SLOT) * 8u, pv);

        // stamped mirror for the overlapped fc (off the critical path):
        // single write per address ever -> 1-bit stamp s&1 (init 0xAA = 2)
        if (cg == 0) {
            const unsigned hw = (__float_as_uint(hv) & ~3u) | (unsigned)(s & 1);
            st_rlx32g(&g_Hs[(size_t)s * 256 + jj], hw);
        }

        m = (m + 1 == MAIL_DEPTH) ? 0 : m + 1;
    }

    // cluster barrier before exit: peers' smem must outlive in-flight pushes
    asm volatile("barrier.cluster.arrive.aligned;" ::: "memory");
    asm volatile("barrier.cluster.wait.aligned;" ::: "memory");
}

// ---------------------------------------------------------------------------
// FC body (overlapped): block handles steps s0..s0+7. Thread tid polls the
// stamped word g_Hs[(s0+i)*256 + tid] (accept when 2 LSBs != 2 = the 0xAA
// init; writer stamps s&1 in {0,1}); nanosleep backoff so co-residency with
// chain CTAs steals no issue slots. Each word is independently validated —
// no cross-address ordering assumed anywhere.
// ---------------------------------------------------------------------------
__device__ void fc_body(
    float* hrow /* 8*256 floats in dynamic smem */, int fcb,
    const float* __restrict__ W_fc, const float* __restrict__ b_fc,
    float* __restrict__ out)
{
    const int tid = threadIdx.x;
    const int s0  = fcb * 8;

#pragma unroll
    for (int i = 0; i < 8; i++) {
        const unsigned* p = &g_Hs[(size_t)(s0 + i) * 256 + tid];
        unsigned u = ld_rlx32g(p);
        while ((u & 3u) == 2u) {      // still the 0xAA init pattern
            __nanosleep(1000);
            u = ld_rlx32g(p);
        }
        hrow[i * 256 + tid] = __uint_as_float(u);
    }
    __syncthreads();

    const int sub = tid >> 7;        // 0/1: steps 0-3 / 4-7
    const int l   = tid & 127;       // label index
    float acc[4];
    const float bias = b_fc[l];
#pragma unroll
    for (int q = 0; q < 4; q++) acc[q] = bias;

    const float* wr = &W_fc[(size_t)l * 256];
    const float* h0 = &hrow[(sub * 4) * 256];
#pragma unroll 4
    for (int j = 0; j < 256; j++) {
        const float wv = wr[j];
#pragma unroll
        for (int q = 0; q < 4; q++)
            acc[q] = fmaf(wv, h0[q * 256 + j], acc[q]);
    }

#pragma unroll
    for (int q = 0; q < 4; q++) {
        const int s = s0 + sub * 4 + q;
        const int t = s >> 6, b = s & 63;
        out[((size_t)b << 14) + (size_t)t * 128 + l] = acc[q];
    }
}

// ---------------------------------------------------------------------------
// Fused kernel: blocks 0..15 = chain cluster; 16..2063 = GEMM tiles;
// 2064..3087 = overlapped fc blocks.
// ---------------------------------------------------------------------------
__global__ void __launch_bounds__(256) fused_kernel(
    const float* __restrict__ x, const float* __restrict__ hi,
    const float* __restrict__ W_ih, const float* __restrict__ W_hh,
    const float* __restrict__ b_ih, const float* __restrict__ b_hh,
    const float* __restrict__ W_fc, const float* __restrict__ b_fc,
    float* __restrict__ out)
{
    extern __shared__ unsigned long long dynsmem[];
    if (blockIdx.x < CHAIN_CTAS) {
        chain_body(dynsmem, blockIdx.x, W_ih, W_hh);
    } else if (blockIdx.x < CHAIN_CTAS + GEMM_BLOCKS) {
        gemm_body((float*)dynsmem, blockIdx.x - CHAIN_CTAS, x, hi, W_ih, b_ih, b_hh);
    } else {
        fc_body((float*)dynsmem, blockIdx.x - (CHAIN_CTAS + GEMM_BLOCKS),
                W_fc, b_fc, out);
    }
}

// ---------------------------------------------------------------------------
extern "C" void kernel_launch(void* const* d_in, const int* in_sizes, int n_in,
                              void* d_out, int out_size)
{
    const float* x    = (const float*)d_in[0];
    const float* hi   = (const float*)d_in[1];
    const float* W_ih = (const float*)d_in[2];
    const float* W_hh = (const float*)d_in[3];
    const float* b_ih = (const float*)d_in[4];
    const float* b_hh = (const float*)d_in[5];
    const float* W_fc = (const float*)d_in[6];
    const float* b_fc = (const float*)d_in[7];
    float* out = (float*)d_out;

    // reset counters and the stamped h mirror (0xAA -> stamp bits = 2) each replay
    void* gp = nullptr;
    cudaGetSymbolAddress(&gp, g_gdone);
    cudaMemsetAsync(gp, 0, 128 * sizeof(unsigned));
    void* hp = nullptr;
    cudaGetSymbolAddress(&hp, g_Hs);
    cudaMemsetAsync(hp, 0xAA, 8192u * 256u * sizeof(unsigned));

    const int smem_bytes = MAIL_DEPTH * MAIL_SLOT * sizeof(unsigned long long); // 77184
    cudaFuncSetAttribute(fused_kernel,
                         cudaFuncAttributeMaxDynamicSharedMemorySize, smem_bytes);
    cudaFuncSetAttribute(fused_kernel,
                         cudaFuncAttributeNonPortableClusterSizeAllowed, 1);

    cudaLaunchConfig_t cfg = {};
    cfg.gridDim  = dim3(CHAIN_CTAS + GEMM_BLOCKS + FC_BLOCKS, 1, 1);  // 3088 = 193*16
    cfg.blockDim = dim3(256, 1, 1);
    cfg.dynamicSmemBytes = smem_bytes;
    cudaLaunchAttribute attrs[1];
    attrs[0].id = cudaLaunchAttributeClusterDimension;
    attrs[0].val.clusterDim.x = 16;
    attrs[0].val.clusterDim.y = 1;
    attrs[0].val.clusterDim.z = 1;
    cfg.attrs = attrs;
    cfg.numAttrs = 1;
    cudaLaunchKernelEx(&cfg, fused_kernel, x, hi, W_ih, W_hh, b_ih, b_hh,
                       W_fc, b_fc, out);
}